// round 17
// baseline (speedup 1.0000x reference)
#include <cuda_runtime.h>
#include <math.h>

#define FULLMASK 0xffffffffu
#define TWO_PI_F 6.2831853071795864f

// ---------------- scratch ----------------
__device__ float g_ts[256 * 256];   // ts angles, row b: [s*64 + g]
__device__ int g_flag[256];         // row-ready flags; 0 at load, restored to 0 each launch

// ---------------- sim14 single-layer op schedule (32 ops) ----------------
__constant__ int c_OPC[32] = {
    -1,-1,-1,-1,-1,-1,-1,-1,
     7, 6, 5, 4, 3, 2, 1, 0,
    -1,-1,-1,-1,-1,-1,-1,-1,
     7, 0, 1, 2, 3, 4, 5, 6};
__constant__ int c_OPT[32] = {
     0, 1, 2, 3, 4, 5, 6, 7,
     0, 7, 6, 5, 4, 3, 2, 1,
     0, 1, 2, 3, 4, 5, 6, 7,
     6, 7, 0, 1, 2, 3, 4, 5};

// ---------------- helpers ----------------
__device__ __forceinline__ float silu_f(float x) { return x * (1.f / (1.f + expf(-x))); }
__device__ __forceinline__ void hbar(int id) {
    asm volatile("bar.sync %0, 128;" :: "r"(id) : "memory");
}

// State layout (4 warps per element; warp index = ancilla s; htid = tid & 127):
//   flat index n (10 bits): bit9..bit5 = wires 0..4 (lane bits 4..0),
//   bit4 = wire5 (reg M=4), bit3 = wire6 (reg M=2), bit2 = wire7 (reg M=1),
//   bit1 = wire8/anc0 (htid bit 6), bit0 = wire9/anc1 (htid bit 5).
//   Each thread holds 8 float2: n = (lane<<5) | (r<<2) | hwarp.
#define OIDX(n) ((n) ^ (((n) >> 5) & 31))

// RY on a lane-bit wire (scalar coeffs)
__device__ __forceinline__ void ry_lane(float2 (&st)[8], int lmask, int lb, int lane,
                                        float c, float s) {
    float sv = ((lane >> lb) & 1) ? s : -s;
#pragma unroll
    for (int r = 0; r < 8; ++r) {
        float ox = __shfl_xor_sync(FULLMASK, st[r].x, lmask);
        float oy = __shfl_xor_sync(FULLMASK, st[r].y, lmask);
        st[r].x = fmaf(c, st[r].x, sv * ox);
        st[r].y = fmaf(c, st[r].y, sv * oy);
    }
}

// RY on a reg-bit wire (mask M in {4,2,1})
template <int M>
__device__ __forceinline__ void ry_reg(float2 (&st)[8], float c, float s) {
#pragma unroll
    for (int r = 0; r < 8; ++r) {
        if ((r & M) == 0) {
            const int r1 = r | M;
            float ax = st[r].x, ay = st[r].y, bx = st[r1].x, by = st[r1].y;
            st[r].x = fmaf(c, ax, -s * bx);
            st[r].y = fmaf(c, ay, -s * by);
            st[r1].x = fmaf(s, ax, c * bx);
            st[r1].y = fmaf(s, ay, c * by);
        }
    }
}

// CRX target=lane wire, control=lane bit
__device__ __forceinline__ void crx_lane(float2 (&st)[8], int tmask, bool act,
                                         float c, float s) {
#pragma unroll
    for (int r = 0; r < 8; ++r) {
        float ox = __shfl_xor_sync(FULLMASK, st[r].x, tmask);
        float oy = __shfl_xor_sync(FULLMASK, st[r].y, tmask);
        float nx = fmaf(c, st[r].x, s * oy);
        float ny = fmaf(c, st[r].y, -s * ox);
        if (act) { st[r].x = nx; st[r].y = ny; }
    }
}

// CRX target=reg wire M, control=lane bit
template <int M>
__device__ __forceinline__ void crx_reg(float2 (&st)[8], bool act, float c, float s) {
#pragma unroll
    for (int r = 0; r < 8; ++r) {
        if ((r & M) == 0) {
            const int r1 = r | M;
            float ax = st[r].x, ay = st[r].y, bx = st[r1].x, by = st[r1].y;
            float n0x = fmaf(c, ax, s * by);
            float n0y = fmaf(c, ay, -s * bx);
            float n1x = fmaf(c, bx, s * ay);
            float n1y = fmaf(c, by, -s * ax);
            if (act) { st[r] = make_float2(n0x, n0y); st[r1] = make_float2(n1x, n1y); }
        }
    }
}

// CRX target=lane wire, control=reg bit CRM (compile-time skip)
template <int CRM>
__device__ __forceinline__ void crx_lane_rc(float2 (&st)[8], int tmask, float c, float s) {
#pragma unroll
    for (int r = 0; r < 8; ++r) {
        if ((r & CRM) != 0) {
            float ox = __shfl_xor_sync(FULLMASK, st[r].x, tmask);
            float oy = __shfl_xor_sync(FULLMASK, st[r].y, tmask);
            st[r].x = fmaf(c, st[r].x, s * oy);
            st[r].y = fmaf(c, st[r].y, -s * ox);
        }
    }
}

// CRX target=reg wire M, control=reg bit CRM (compile-time skip)
template <int M, int CRM>
__device__ __forceinline__ void crx_reg_rc(float2 (&st)[8], float c, float s) {
#pragma unroll
    for (int r = 0; r < 8; ++r) {
        if ((r & M) == 0 && (r & CRM) != 0) {
            const int r1 = r | M;
            float ax = st[r].x, ay = st[r].y, bx = st[r1].x, by = st[r1].y;
            st[r].x  = fmaf(c, ax, s * by);
            st[r].y  = fmaf(c, ay, -s * bx);
            st[r1].x = fmaf(c, bx, s * ay);
            st[r1].y = fmaf(c, by, -s * ax);
        }
    }
}

// warp-uniform diagonal: v *= (c + i*ss)
__device__ __forceinline__ void rz_w(float2 (&st)[8], float c, float ss) {
#pragma unroll
    for (int r = 0; r < 8; ++r) {
        float x = st[r].x, y = st[r].y;
        st[r].x = fmaf(c, x, -ss * y);
        st[r].y = fmaf(c, y, ss * x);
    }
}

// RY on a warp bit (xm = 64 for w8, 32 for w9): smem exchange (per-half barrier)
__device__ __forceinline__ void prep_ry(float2 (&st)[8], float2* sbuf, int htid, int bid,
                                        int xm, float c, float s) {
    hbar(bid);
#pragma unroll
    for (int r = 0; r < 8; ++r) sbuf[r * 128 + htid] = st[r];
    hbar(bid);
    const int p = htid ^ xm;
    const float sg = (htid & xm) ? s : -s;
#pragma unroll
    for (int r = 0; r < 8; ++r) {
        float2 o = sbuf[r * 128 + p];
        st[r].x = fmaf(c, st[r].x, sg * o.x);
        st[r].y = fmaf(c, st[r].y, sg * o.y);
    }
}

// CNOT(control=w8, target=w9): warps 2<->3 swap (per-half barrier)
__device__ __forceinline__ void cnot_w(float2 (&st)[8], float2* sbuf, int htid, int bid) {
    hbar(bid);
#pragma unroll
    for (int r = 0; r < 8; ++r) sbuf[r * 128 + htid] = st[r];
    hbar(bid);
    if (htid & 64) {
        const int p = htid ^ 32;
#pragma unroll
        for (int r = 0; r < 8; ++r) st[r] = sbuf[r * 128 + p];
    }
}

__device__ __forceinline__ void apply_op(float2 (&st)[8], int lane,
                                         int cw, int tw, float c, float s) {
    if (cw < 0) {  // RY
        if (tw < 5)       ry_lane(st, 1 << (4 - tw), 4 - tw, lane, c, s);
        else if (tw == 5) ry_reg<4>(st, c, s);
        else if (tw == 6) ry_reg<2>(st, c, s);
        else              ry_reg<1>(st, c, s);
    } else if (cw < 5) {   // lane control
        bool act = ((lane >> (4 - cw)) & 1) != 0;
        if (tw < 5)       crx_lane(st, 1 << (4 - tw), act, c, s);
        else if (tw == 5) crx_reg<4>(st, act, c, s);
        else if (tw == 6) crx_reg<2>(st, act, c, s);
        else              crx_reg<1>(st, act, c, s);
    } else if (cw == 5) {  // control = reg bit 4
        if (tw == 6)      crx_reg_rc<2, 4>(st, c, s);        // (5,6)
        else              crx_lane_rc<4>(st, 1, c, s);       // (5,4): lane bit 0
    } else if (cw == 6) {  // control = reg bit 2
        if (tw == 7)      crx_reg_rc<1, 2>(st, c, s);        // (6,7)
        else              crx_reg_rc<4, 2>(st, c, s);        // (6,5)
    } else {               // cw == 7, control = reg bit 1
        if (tw == 0)      crx_lane_rc<1>(st, 16, c, s);      // (7,0): lane bit 4
        else              crx_reg_rc<2, 1>(st, c, s);        // (7,6)
    }
}

// sim14 with 2 layers; per-warp scalar coefficients from tab[step*4 + hwarp]
__device__ __forceinline__ void run_sim14_2l(float2 (&st)[8], int lane, int hwarp,
                                             const float2* tab, bool adj) {
    if (!adj) {
#pragma unroll 1
        for (int step = 0; step < 64; ++step) {
            int o = step & 31;
            float2 cs = tab[step * 4 + hwarp];
            apply_op(st, lane, c_OPC[o], c_OPT[o], cs.x, cs.y);
        }
    } else {
#pragma unroll 1
        for (int step = 63; step >= 0; --step) {
            int o = step & 31;
            float2 cs = tab[step * 4 + hwarp];
            apply_op(st, lane, c_OPC[o], c_OPT[o], cs.x, -cs.y);
        }
    }
}

// prepare on ancilla wires 8,9 (warp bits)
__device__ __forceinline__ void do_prepare(float2 (&st)[8], float2* sbuf, int htid, int bid,
                                           const float2* tabp, bool adj) {
    if (!adj) {
#pragma unroll
        for (int ly = 0; ly < 2; ++ly) {
            float2 a  = tabp[ly*4+0]; prep_ry(st, sbuf, htid, bid, 64, a.x, a.y);
            float2 z  = tabp[ly*4+1]; rz_w(st, z.x, (htid & 64) ? z.y : -z.y);
            float2 a2 = tabp[ly*4+2]; prep_ry(st, sbuf, htid, bid, 32, a2.x, a2.y);
            float2 z2 = tabp[ly*4+3]; rz_w(st, z2.x, (htid & 32) ? z2.y : -z2.y);
            cnot_w(st, sbuf, htid, bid);
        }
    } else {
#pragma unroll
        for (int ly = 1; ly >= 0; --ly) {
            cnot_w(st, sbuf, htid, bid);
            float2 z2 = tabp[ly*4+3]; rz_w(st, z2.x, (htid & 32) ? -z2.y : z2.y);
            float2 a2 = tabp[ly*4+2]; prep_ry(st, sbuf, htid, bid, 32, a2.x, -a2.y);
            float2 z  = tabp[ly*4+1]; rz_w(st, z.x, (htid & 64) ? -z.y : z.y);
            float2 a  = tabp[ly*4+0]; prep_ry(st, sbuf, htid, bid, 64, a.x, -a.y);
        }
    }
}

// ---------------- single fused kernel: blocks 0-127 MLP, blocks 128-255 sim ----------------
__global__ void __launch_bounds__(256) k_all(
    const float* __restrict__ t, const float* __restrict__ z_t,
    const float* __restrict__ te_w1, const float* __restrict__ te_b1,
    const float* __restrict__ te_w2, const float* __restrict__ te_b2,
    const float* __restrict__ ip_w1, const float* __restrict__ ip_b1,
    const float* __restrict__ ip_w2, const float* __restrict__ ip_b2,
    const float* __restrict__ prep_p, const float* __restrict__ sig,
    const float* __restrict__ qff,
    const float* __restrict__ A_obs, const float* __restrict__ B_obs,
    const float* __restrict__ D_obs,
    const float* __restrict__ head_w, const float* __restrict__ head_b,
    float* __restrict__ out) {
    // MLP smem
    __shared__ float emb[2][128];
    __shared__ float hb[2][128];
    __shared__ float cat[2][256];
    __shared__ float g1m[2][256];
    // sim smem (per half)
    __shared__ float2 sbuf2[2][1024];
    __shared__ float2 tabsel2[2][256];
    __shared__ float2 tabq2[2][32];
    __shared__ float2 tabp2[2][8];
    __shared__ float2 tabsig2[2][4];
    __shared__ float part2[2][28];

    const int tid = threadIdx.x;

    if (blockIdx.x < 128) {
        // ================= MLP (round-2 exact) =================
        const int r0 = blockIdx.x * 2;

        // stage A: sinusoidal embedding + copy z_t into cat
        {
            int row = tid >> 7, i = tid & 127;
            float tv = t[r0 + row];
            int ii = i & 63;
            float f = expf(-0.14391156831212787f * (float)ii);
            float a = tv * f;
            emb[row][i] = (i < 64) ? cosf(a) : sinf(a);
            cat[row][i] = z_t[(r0 + row) * 128 + i];
        }
        __syncthreads();

        // stage B: h = silu(te_w1 @ emb + te_b1)
        if (tid < 128) {
            int j = tid;
            float a0 = te_b1[j], a1 = a0;
            const float4* w4 = reinterpret_cast<const float4*>(te_w1 + j * 128);
#pragma unroll 8
            for (int k4 = 0; k4 < 32; ++k4) {
                float4 wv = w4[k4];
                float4 x0 = *reinterpret_cast<const float4*>(&emb[0][k4 * 4]);
                float4 x1 = *reinterpret_cast<const float4*>(&emb[1][k4 * 4]);
                a0 = fmaf(wv.x, x0.x, a0); a0 = fmaf(wv.y, x0.y, a0);
                a0 = fmaf(wv.z, x0.z, a0); a0 = fmaf(wv.w, x0.w, a0);
                a1 = fmaf(wv.x, x1.x, a1); a1 = fmaf(wv.y, x1.y, a1);
                a1 = fmaf(wv.z, x1.z, a1); a1 = fmaf(wv.w, x1.w, a1);
            }
            hb[0][j] = silu_f(a0); hb[1][j] = silu_f(a1);
        }
        __syncthreads();

        // stage C: t_emb2 = te_w2 @ h + te_b2 -> cat[., 128+j]
        if (tid < 128) {
            int j = tid;
            float a0 = te_b2[j], a1 = a0;
            const float4* w4 = reinterpret_cast<const float4*>(te_w2 + j * 128);
#pragma unroll 8
            for (int k4 = 0; k4 < 32; ++k4) {
                float4 wv = w4[k4];
                float4 x0 = *reinterpret_cast<const float4*>(&hb[0][k4 * 4]);
                float4 x1 = *reinterpret_cast<const float4*>(&hb[1][k4 * 4]);
                a0 = fmaf(wv.x, x0.x, a0); a0 = fmaf(wv.y, x0.y, a0);
                a0 = fmaf(wv.z, x0.z, a0); a0 = fmaf(wv.w, x0.w, a0);
                a1 = fmaf(wv.x, x1.x, a1); a1 = fmaf(wv.y, x1.y, a1);
                a1 = fmaf(wv.z, x1.z, a1); a1 = fmaf(wv.w, x1.w, a1);
            }
            cat[0][128 + j] = a0; cat[1][128 + j] = a1;
        }
        __syncthreads();

        // stage D: g1 = silu(ip_w1 @ cat + ip_b1)
        {
            int j = tid;
            float a0 = ip_b1[j], a1 = a0;
            const float4* w4 = reinterpret_cast<const float4*>(ip_w1 + j * 256);
#pragma unroll 8
            for (int k4 = 0; k4 < 64; ++k4) {
                float4 wv = w4[k4];
                float4 x0 = *reinterpret_cast<const float4*>(&cat[0][k4 * 4]);
                float4 x1 = *reinterpret_cast<const float4*>(&cat[1][k4 * 4]);
                a0 = fmaf(wv.x, x0.x, a0); a0 = fmaf(wv.y, x0.y, a0);
                a0 = fmaf(wv.z, x0.z, a0); a0 = fmaf(wv.w, x0.w, a0);
                a1 = fmaf(wv.x, x1.x, a1); a1 = fmaf(wv.y, x1.y, a1);
                a1 = fmaf(wv.z, x1.z, a1); a1 = fmaf(wv.w, x1.w, a1);
            }
            g1m[0][j] = silu_f(a0); g1m[1][j] = silu_f(a1);
        }
        __syncthreads();

        // stage E: ts = sigmoid(ip_w2 @ g1 + ip_b2) * 2pi
        {
            int j = tid;
            float a0 = ip_b2[j], a1 = a0;
            const float4* w4 = reinterpret_cast<const float4*>(ip_w2 + j * 256);
#pragma unroll 8
            for (int k4 = 0; k4 < 64; ++k4) {
                float4 wv = w4[k4];
                float4 x0 = *reinterpret_cast<const float4*>(&g1m[0][k4 * 4]);
                float4 x1 = *reinterpret_cast<const float4*>(&g1m[1][k4 * 4]);
                a0 = fmaf(wv.x, x0.x, a0); a0 = fmaf(wv.y, x0.y, a0);
                a0 = fmaf(wv.z, x0.z, a0); a0 = fmaf(wv.w, x0.w, a0);
                a1 = fmaf(wv.x, x1.x, a1); a1 = fmaf(wv.y, x1.y, a1);
                a1 = fmaf(wv.z, x1.z, a1); a1 = fmaf(wv.w, x1.w, a1);
            }
            g_ts[r0 * 256 + j]       = TWO_PI_F / (1.f + expf(-a0));
            g_ts[(r0 + 1) * 256 + j] = TWO_PI_F / (1.f + expf(-a1));
        }
        // release: make g_ts visible, then set flags
        __threadfence();
        __syncthreads();
        if (tid == 0) {
            atomicExch(&g_flag[r0], 1);
            atomicExch(&g_flag[r0 + 1], 1);
        }
        return;
    }

    // ================= sim: 2 independent elements per block =================
    const int e     = blockIdx.x - 128;
    const int lane  = tid & 31;
    const int half  = tid >> 7;
    const int htid  = tid & 127;
    const int hwarp = htid >> 5;
    const int bid   = half + 1;
    const int b     = e * 2 + half;

    // wait for this row's ts (flag set by MLP block; cleared below for next replay)
    {
        volatile int* vf = &g_flag[b];
        while (*vf == 0) __nanosleep(128);
    }
    __threadfence();

    const float* tsr = g_ts + b * 256;
    float2* sbuf = sbuf2[half];
    float2* tabsel = tabsel2[half];

    // tables: tsr index i = s*64 + g -> tabsel[g*4 + s]
#pragma unroll
    for (int u = 0; u < 2; ++u) {
        int i = htid + u * 128;
        int s = i >> 6, g = i & 63;
        float sn, cc; sincosf(tsr[i] * 0.5f, &sn, &cc);
        tabsel[g * 4 + s] = make_float2(cc, sn);
    }
    if (htid < 32)      { float sn, cc; sincosf(qff[htid] * 0.5f, &sn, &cc); tabq2[half][htid] = make_float2(cc, sn); }
    else if (htid < 40) { int q = htid - 32; float sn, cc; sincosf(prep_p[q] * 0.5f, &sn, &cc); tabp2[half][q] = make_float2(cc, sn); }
    else if (htid < 44) { int q = htid - 40; float sn, cc; sincosf(sig[q], &sn, &cc); tabsig2[half][q] = make_float2(cc, sn); }
    hbar(bid);
    if (htid == 0) *((volatile int*)&g_flag[b]) = 0;   // reset for next replay

    const float2* tabq = tabq2[half];
    const float2* tabp = tabp2[half];
    const float2* tabsig = tabsig2[half];

    float2 st[8];
#pragma unroll
    for (int r = 0; r < 8; ++r) st[r] = make_float2(0.f, 0.f);
    if (htid == 0) st[0].x = 1.f;

    // pcphase(sig[0]): warp 0 (anc=0) gets +phi
    { float2 p = tabsig[0]; rz_w(st, p.x, (hwarp == 0) ? p.y : -p.y); }
#pragma unroll 1
    for (int k = 0; k < 3; ++k) {
        do_prepare(st, sbuf, htid, bid, tabp, false);
        run_sim14_2l(st, lane, hwarp, tabsel, (k & 1) != 0);
        do_prepare(st, sbuf, htid, bid, tabp, true);
        float2 p = tabsig[k + 1];
        rz_w(st, p.x, (hwarp == 0) ? p.y : -p.y);
    }
    // final sim14 with qff params, 1 layer (uniform theta)
#pragma unroll 1
    for (int step = 0; step < 32; ++step) {
        float2 tq = tabq[step];
        apply_op(st, lane, c_OPC[step], c_OPT[step], tq.x, tq.y);
    }

    // dump state to shared (swizzled) for expectation values
    hbar(bid);
#pragma unroll
    for (int r = 0; r < 8; ++r) {
        int n = (lane << 5) | (r << 2) | hwarp;
        sbuf[OIDX(n)] = st[r];
    }
    hbar(bid);

#pragma unroll 1
    for (int w = 0; w < 7; ++w) {
        const float* Aw = A_obs + w * 6;
        const float* Bw = B_obs + w * 6;
        const float* Dw = D_obs + w * 4;
        float d0 = 2.f * Dw[1], d1 = 2.f * Dw[2], d2 = 2.f * Dw[3];
        float a10 = Aw[0], b10 = Bw[0], a20 = Aw[1], b20 = Bw[1], a21 = Aw[2], b21 = Bw[2];
        float a30 = Aw[3], b30 = Bw[3], a31 = Aw[4], b31 = Bw[4], a32 = Aw[5], b32 = Bw[5];
        int b1 = 8 - w;
        int m1 = 1 << b1, m0 = m1 << 1;
        int lowmask = m1 - 1;
        float acc = 0.f;
#pragma unroll
        for (int it = 0; it < 2; ++it) {
            int gi = htid + it * 128;
            int n = ((gi & ~lowmask) << 2) | (gi & lowmask);
            float2 v0 = sbuf[OIDX(n)];
            float2 v1 = sbuf[OIDX(n + m1)];
            float2 v2 = sbuf[OIDX(n + m0)];
            float2 v3 = sbuf[OIDX(n + m0 + m1)];
            acc += d0 * (v0.x * v0.x + v0.y * v0.y);
            acc += d1 * (v1.x * v1.x + v1.y * v1.y);
            acc += d2 * (v2.x * v2.x + v2.y * v2.y);
#define CROSS(vi, vj, aa, bb) { \
            float pr = vi.x * vj.x + vi.y * vj.y; \
            float pim = vi.x * vj.y - vi.y * vj.x; \
            acc += 2.f * (pr * (aa) - pim * (bb)); }
            CROSS(v1, v0, a10, b10)
            CROSS(v2, v0, a20, b20)
            CROSS(v2, v1, a21, b21)
            CROSS(v3, v0, a30, b30)
            CROSS(v3, v1, a31, b31)
            CROSS(v3, v2, a32, b32)
#undef CROSS
        }
#pragma unroll
        for (int off = 16; off; off >>= 1) acc += __shfl_xor_sync(FULLMASK, acc, off);
        if (lane == 0) part2[half][w * 4 + hwarp] = acc;
    }
    hbar(bid);

    // head: out[b][j] = sum_w e[w] * head_w[j*7+w] + head_b[j]
    {
        int j = htid;
        float o = head_b[j];
        const float* pp = part2[half];
#pragma unroll
        for (int w = 0; w < 7; ++w) {
            float ev = pp[w*4] + pp[w*4+1] + pp[w*4+2] + pp[w*4+3];
            o = fmaf(ev, head_w[j * 7 + w], o);
        }
        out[b * 128 + j] = o;
    }
}

// ---------------- launch ----------------
extern "C" void kernel_launch(void* const* d_in, const int* in_sizes, int n_in,
                              void* d_out, int out_size) {
    const float* z_t    = (const float*)d_in[0];
    const float* t      = (const float*)d_in[1];
    const float* te_w1  = (const float*)d_in[2];
    const float* te_b1  = (const float*)d_in[3];
    const float* te_w2  = (const float*)d_in[4];
    const float* te_b2  = (const float*)d_in[5];
    const float* ip_w1  = (const float*)d_in[6];
    const float* ip_b1  = (const float*)d_in[7];
    const float* ip_w2  = (const float*)d_in[8];
    const float* ip_b2  = (const float*)d_in[9];
    const float* prep   = (const float*)d_in[10];
    const float* sig    = (const float*)d_in[11];
    const float* qff    = (const float*)d_in[12];
    const float* A_obs  = (const float*)d_in[13];
    const float* B_obs  = (const float*)d_in[14];
    const float* D_obs  = (const float*)d_in[15];
    const float* head_w = (const float*)d_in[16];
    const float* head_b = (const float*)d_in[17];
    float* out = (float*)d_out;

    k_all<<<256, 256>>>(t, z_t, te_w1, te_b1, te_w2, te_b2, ip_w1, ip_b1, ip_w2, ip_b2,
                        prep, sig, qff, A_obs, B_obs, D_obs, head_w, head_b, out);
}